// round 7
// baseline (speedup 1.0000x reference)
#include <cuda_runtime.h>
#include <cuda_fp16.h>
#include <cstdint>

#define DINL __device__ __forceinline__

namespace {
constexpr int Tn = 187;
constexpr int Hn = 256;
constexpr int BM = 128;          // batch rows per CTA
constexpr int NT = 256;          // threads per CTA (8 warps x 16 rows)

constexpr int WH_STRIDE = 528;   // bytes per Wh row (264 f16: 512 + 16 pad -> conflict-free ldsm)
constexpr int W1_STRIDE = 144;   // bytes per W1 row (72 f16)
constexpr int X_STRIDE  = 192;   // f16 per x row

constexpr int OFF_WH  = 0;
constexpr int OFF_W1  = OFF_WH + Hn * WH_STRIDE;        // 135168
constexpr int OFF_X   = OFF_W1 + Hn * W1_STRIDE;        // 172032
constexpr int OFF_WXB = OFF_X  + BM * X_STRIDE * 2;     // 221184  (float2 {Wx,b} x256)
constexpr int OFF_B1  = OFF_WXB + Hn * 8;               // 223232
constexpr int OFF_W2  = OFF_B1 + 64 * 4;                // 223488
constexpr int OFF_B2  = OFF_W2 + 320 * 4;               // 224768
constexpr int SMEM_TOTAL = OFF_B2 + 32;                 // 224800
static_assert(SMEM_TOTAL <= 232448, "smem overflow");
}

// ---------------- helpers ----------------
DINL uint32_t smem_u32(const void* p) {
    uint32_t a;
    asm("{ .reg .u64 t; cvta.to.shared.u64 t, %1; cvt.u32.u64 %0, t; }" : "=r"(a) : "l"(p));
    return a;
}
DINL void ldsm4t(uint32_t& r0, uint32_t& r1, uint32_t& r2, uint32_t& r3, uint32_t addr) {
    asm volatile("ldmatrix.sync.aligned.m8n8.x4.trans.shared.b16 {%0,%1,%2,%3}, [%4];"
                 : "=r"(r0), "=r"(r1), "=r"(r2), "=r"(r3) : "r"(addr));
}
DINL void mma16816(float* d, uint32_t a0, uint32_t a1, uint32_t a2, uint32_t a3,
                   uint32_t b0, uint32_t b1) {
    asm volatile("mma.sync.aligned.m16n8k16.row.col.f32.f16.f16.f32 "
                 "{%0,%1,%2,%3}, {%4,%5,%6,%7}, {%8,%9}, {%0,%1,%2,%3};"
                 : "+f"(d[0]), "+f"(d[1]), "+f"(d[2]), "+f"(d[3])
                 : "r"(a0), "r"(a1), "r"(a2), "r"(a3), "r"(b0), "r"(b1));
}
DINL uint32_t pack_f16x2(float lo, float hi) {
    uint32_t r;
    asm("cvt.rn.f16x2.f32 %0, %1, %2;" : "=r"(r) : "f"(hi), "f"(lo));
    return r;
}
DINL uint32_t tanh2(uint32_t v) {
    uint32_t r;
    asm("tanh.approx.f16x2 %0, %1;" : "=r"(r) : "r"(v));
    return r;
}

// One RNN step: hOut = tanh(x*Wx + b + hIn @ Wh), all fragments register-resident.
DINL void rnn_step(uint32_t lds_wh, const float4* __restrict__ wxb4, int tig,
                   float xg, float xg8, uint32_t (&hIn)[64], uint32_t (&hOut)[64]) {
    #pragma unroll
    for (int g = 0; g < 4; ++g) {            // 64-col n-group: n8-tiles 8g..8g+7
        float d[8][4];
        #pragma unroll
        for (int j = 0; j < 8; ++j) {        // D init = x_t*Wx + b (folds epilogue add)
            float4 wb = wxb4[4 * (8 * g + j) + tig];
            d[j][0] = fmaf(xg,  wb.x, wb.y);
            d[j][1] = fmaf(xg,  wb.z, wb.w);
            d[j][2] = fmaf(xg8, wb.x, wb.y);
            d[j][3] = fmaf(xg8, wb.z, wb.w);
        }
        #pragma unroll
        for (int kc = 0; kc < 16; ++kc) {
            const uint32_t a0 = hIn[4 * kc], a1 = hIn[4 * kc + 1];
            const uint32_t a2 = hIn[4 * kc + 2], a3 = hIn[4 * kc + 3];
            const uint32_t base = lds_wh + kc * 16 * WH_STRIDE + g * 128;
            #pragma unroll
            for (int q = 0; q < 4; ++q) {    // 2 n8-tiles per ldsm.x4
                uint32_t b0, b1, b2, b3;
                ldsm4t(b0, b1, b2, b3, base + q * 32);
                mma16816(d[2 * q],     a0, a1, a2, a3, b0, b1);
                mma16816(d[2 * q + 1], a0, a1, a2, a3, b2, b3);
            }
        }
        #pragma unroll
        for (int j = 0; j < 8; ++j) {        // pack -> 2-wide tanh -> directly into hOut
            int t2 = 8 * g + j;
            hOut[2 * t2]     = tanh2(pack_f16x2(d[j][0], d[j][1]));
            hOut[2 * t2 + 1] = tanh2(pack_f16x2(d[j][2], d[j][3]));
        }
    }
}

// ---------------- kernel ----------------
__global__ void __launch_bounds__(NT, 1)
rnn_kernel(const float* __restrict__ gx,  const float* __restrict__ gWx,
           const float* __restrict__ gWh, const float* __restrict__ gbr,
           const float* __restrict__ gW1, const float* __restrict__ gb1,
           const float* __restrict__ gW2, const float* __restrict__ gb2,
           float* __restrict__ gout) {
    extern __shared__ char smem[];
    const int tid  = threadIdx.x;
    const int lane = tid & 31;
    const int wid  = tid >> 5;
    const int m0   = blockIdx.x * BM;
    const int gid  = lane >> 2;      // row group 0..7
    const int tig  = lane & 3;       // thread-in-group

    // ---- cooperative staging ----
    for (int i = tid; i < Hn * Hn; i += NT) {            // Wh[k][n] -> k-major padded f16
        int k = i >> 8, n = i & 255;
        *(__half*)(smem + OFF_WH + k * WH_STRIDE + n * 2) = __float2half(gWh[i]);
    }
    for (int i = tid; i < Hn * 64; i += NT) {            // W1[k][n]
        int k = i >> 6, n = i & 63;
        *(__half*)(smem + OFF_W1 + k * W1_STRIDE + n * 2) = __float2half(gW1[i]);
    }
    for (int i = tid; i < BM * Tn; i += NT) {            // x tile, f16
        int r = i / Tn, t = i - r * Tn;
        ((__half*)(smem + OFF_X))[r * X_STRIDE + t] = __float2half(gx[(size_t)(m0 + r) * Tn + t]);
    }
    for (int i = tid; i < Hn; i += NT)
        ((float2*)(smem + OFF_WXB))[i] = make_float2(gWx[i], gbr[i]);
    for (int i = tid; i < 64; i += NT)  ((float*)(smem + OFF_B1))[i] = gb1[i];
    for (int i = tid; i < 320; i += NT) ((float*)(smem + OFF_W2))[i] = gW2[i];
    if (tid < 5) ((float*)(smem + OFF_B2))[tid] = gb2[tid];
    __syncthreads();   // the ONLY barrier in the kernel

    // ---- per-warp setup ----
    const uint32_t sb = smem_u32(smem);
    const int tq = lane >> 3;   // ldmatrix x4 slot
    const uint32_t lds_wh = sb + OFF_WH + ((tq & 1) * 8 + (lane & 7)) * WH_STRIDE + (tq >> 1) * 16;
    const uint32_t lds_w1 = sb + OFF_W1 + ((tq & 1) * 8 + (lane & 7)) * W1_STRIDE + (tq >> 1) * 16;
    const __half* xr0 = (const __half*)(smem + OFF_X) + (wid * 16 + gid) * X_STRIDE;
    const __half* xr8 = xr0 + 8 * X_STRIDE;
    const float4* wxb4 = (const float4*)(smem + OFF_WXB);   // {w0,b0,w1,b1} per even col pair

    uint32_t hA[64], hB[64];   // ping-pong A fragments

    // ---- t = 0: h0 = tanh(x0*Wx + b) -> hA ----
    {
        float xg = __half2float(xr0[0]), xg8 = __half2float(xr8[0]);
        #pragma unroll
        for (int t2 = 0; t2 < 32; ++t2) {
            float4 wb = wxb4[4 * t2 + tig];
            hA[2 * t2]     = tanh2(pack_f16x2(fmaf(xg,  wb.x, wb.y), fmaf(xg,  wb.z, wb.w)));
            hA[2 * t2 + 1] = tanh2(pack_f16x2(fmaf(xg8, wb.x, wb.y), fmaf(xg8, wb.z, wb.w)));
        }
    }

    // ---- recurrence: t = 1..186 as 93 ping-pong pairs (warp-private, no sync) ----
    #pragma unroll 1
    for (int it = 0; it < 93; ++it) {
        int t1 = 2 * it + 1;
        rnn_step(lds_wh, wxb4, tig,
                 __half2float(xr0[t1]),     __half2float(xr8[t1]),     hA, hB);
        rnn_step(lds_wh, wxb4, tig,
                 __half2float(xr0[t1 + 1]), __half2float(xr8[t1 + 1]), hB, hA);
    }

    // ---- head: hidden = relu(h @ W1 + b1) via mma, then W2 + softmax per thread ----
    float hd[8][4];
    #pragma unroll
    for (int t2 = 0; t2 < 8; ++t2)
        hd[t2][0] = hd[t2][1] = hd[t2][2] = hd[t2][3] = 0.f;
    #pragma unroll
    for (int kc = 0; kc < 16; ++kc) {
        const uint32_t a0 = hA[4 * kc], a1 = hA[4 * kc + 1];
        const uint32_t a2 = hA[4 * kc + 2], a3 = hA[4 * kc + 3];
        const uint32_t base = lds_w1 + kc * 16 * W1_STRIDE;
        #pragma unroll
        for (int nt2 = 0; nt2 < 4; ++nt2) {
            uint32_t b0, b1, b2, b3;
            ldsm4t(b0, b1, b2, b3, base + nt2 * 32);
            mma16816(hd[2 * nt2],     a0, a1, a2, a3, b0, b1);
            mma16816(hd[2 * nt2 + 1], a0, a1, a2, a3, b2, b3);
        }
    }
    {
        const float* sb1 = (const float*)(smem + OFF_B1);
        const float* sw2 = (const float*)(smem + OFF_W2);
        const float* sb2 = (const float*)(smem + OFF_B2);
        float acc0[5] = {0, 0, 0, 0, 0}, acc8[5] = {0, 0, 0, 0, 0};
        #pragma unroll
        for (int t2 = 0; t2 < 8; ++t2) {
            int c0 = 8 * t2 + 2 * tig;
            float b1a = sb1[c0], b1b = sb1[c0 + 1];
            float h00 = fmaxf(hd[t2][0] + b1a, 0.f), h01 = fmaxf(hd[t2][1] + b1b, 0.f);
            float h80 = fmaxf(hd[t2][2] + b1a, 0.f), h81 = fmaxf(hd[t2][3] + b1b, 0.f);
            #pragma unroll
            for (int c = 0; c < 5; ++c) {
                acc0[c] = fmaf(h00, sw2[c0 * 5 + c], fmaf(h01, sw2[(c0 + 1) * 5 + c], acc0[c]));
                acc8[c] = fmaf(h80, sw2[c0 * 5 + c], fmaf(h81, sw2[(c0 + 1) * 5 + c], acc8[c]));
            }
        }
        #pragma unroll
        for (int c = 0; c < 5; ++c) {                   // reduce over 4-lane tig group
            acc0[c] += __shfl_xor_sync(0xFFFFFFFFu, acc0[c], 1);
            acc0[c] += __shfl_xor_sync(0xFFFFFFFFu, acc0[c], 2);
            acc8[c] += __shfl_xor_sync(0xFFFFFFFFu, acc8[c], 1);
            acc8[c] += __shfl_xor_sync(0xFFFFFFFFu, acc8[c], 2);
        }
        if (tig == 0) {
            int row0 = m0 + wid * 16 + gid;
            float o[5];
            #pragma unroll
            for (int c = 0; c < 5; ++c) o[c] = acc0[c] + sb2[c];
            float mx = fmaxf(fmaxf(fmaxf(o[0], o[1]), fmaxf(o[2], o[3])), o[4]);
            float s = 0.f;
            #pragma unroll
            for (int c = 0; c < 5; ++c) { o[c] = __expf(o[c] - mx); s += o[c]; }
            float inv = 1.f / s;
            #pragma unroll
            for (int c = 0; c < 5; ++c) gout[(size_t)row0 * 5 + c] = o[c] * inv;

            #pragma unroll
            for (int c = 0; c < 5; ++c) o[c] = acc8[c] + sb2[c];
            mx = fmaxf(fmaxf(fmaxf(o[0], o[1]), fmaxf(o[2], o[3])), o[4]);
            s = 0.f;
            #pragma unroll
            for (int c = 0; c < 5; ++c) { o[c] = __expf(o[c] - mx); s += o[c]; }
            inv = 1.f / s;
            #pragma unroll
            for (int c = 0; c < 5; ++c) gout[(size_t)(row0 + 8) * 5 + c] = o[c] * inv;
        }
    }
}

// ---------------- launch ----------------
extern "C" void kernel_launch(void* const* d_in, const int* in_sizes, int n_in,
                              void* d_out, int out_size) {
    const float* x  = (const float*)d_in[0];
    const float* Wx = (const float*)d_in[1];
    const float* Wh = (const float*)d_in[2];
    const float* br = (const float*)d_in[3];
    const float* W1 = (const float*)d_in[4];
    const float* b1 = (const float*)d_in[5];
    const float* W2 = (const float*)d_in[6];
    const float* b2 = (const float*)d_in[7];

    cudaFuncSetAttribute(rnn_kernel, cudaFuncAttributeMaxDynamicSharedMemorySize, SMEM_TOTAL);
    rnn_kernel<<<256, NT, SMEM_TOTAL>>>(x, Wx, Wh, br, W1, b1, W2, b2, (float*)d_out);
}

// round 8
// speedup vs baseline: 2.5772x; 2.5772x over previous
#include <cuda_runtime.h>
#include <cuda_fp16.h>
#include <cstdint>

#define DINL __device__ __forceinline__

namespace {
constexpr int Tn = 187;
constexpr int Hn = 256;
constexpr int BM = 128;          // batch rows per CTA
constexpr int NT = 256;          // 8 warps; warp = (row-half, col-quarter) of 128x256

constexpr int WH_STRIDE = 528;   // bytes per Wh row (264 f16) -> conflict-free ldsm
constexpr int H_STRIDE  = 528;   // bytes per h row
constexpr int W1_STRIDE = 144;   // bytes per W1 row (72 f16)

constexpr int OFF_WH  = 0;                          // 256*528 = 135168 (W1 staged here later)
constexpr int OFF_H   = OFF_WH + Hn * WH_STRIDE;    // 135168, h buffer 128*528 = 67584
constexpr int OFF_WXB = OFF_H + BM * H_STRIDE;      // 202752, float2{Wx,b} x256 = 2048
constexpr int OFF_B1  = OFF_WXB + Hn * 8;           // 204800
constexpr int OFF_W2  = OFF_B1 + 64 * 4;            // 205056
constexpr int OFF_B2  = OFF_W2 + 320 * 4;           // 206336
constexpr int SMEM_TOTAL = OFF_B2 + 32;             // 206368
static_assert(SMEM_TOTAL <= 232448, "smem overflow");
}

// ---------------- helpers ----------------
DINL uint32_t smem_u32(const void* p) {
    uint32_t a;
    asm("{ .reg .u64 t; cvta.to.shared.u64 t, %1; cvt.u32.u64 %0, t; }" : "=r"(a) : "l"(p));
    return a;
}
DINL void ldsm4(uint32_t& r0, uint32_t& r1, uint32_t& r2, uint32_t& r3, uint32_t addr) {
    asm volatile("ldmatrix.sync.aligned.m8n8.x4.shared.b16 {%0,%1,%2,%3}, [%4];"
                 : "=r"(r0), "=r"(r1), "=r"(r2), "=r"(r3) : "r"(addr));
}
DINL void ldsm4t(uint32_t& r0, uint32_t& r1, uint32_t& r2, uint32_t& r3, uint32_t addr) {
    asm volatile("ldmatrix.sync.aligned.m8n8.x4.trans.shared.b16 {%0,%1,%2,%3}, [%4];"
                 : "=r"(r0), "=r"(r1), "=r"(r2), "=r"(r3) : "r"(addr));
}
DINL void mma16816(float* d, uint32_t a0, uint32_t a1, uint32_t a2, uint32_t a3,
                   uint32_t b0, uint32_t b1) {
    asm volatile("mma.sync.aligned.m16n8k16.row.col.f32.f16.f16.f32 "
                 "{%0,%1,%2,%3}, {%4,%5,%6,%7}, {%8,%9}, {%0,%1,%2,%3};"
                 : "+f"(d[0]), "+f"(d[1]), "+f"(d[2]), "+f"(d[3])
                 : "r"(a0), "r"(a1), "r"(a2), "r"(a3), "r"(b0), "r"(b1));
}
DINL uint32_t pack_f16x2(float lo, float hi) {
    uint32_t r;
    asm("cvt.rn.f16x2.f32 %0, %1, %2;" : "=r"(r) : "f"(hi), "f"(lo));
    return r;
}
DINL uint32_t tanh2(uint32_t v) {
    uint32_t r;
    asm("tanh.approx.f16x2 %0, %1;" : "=r"(r) : "r"(v));
    return r;
}
DINL void bar_sync(int id, int nthreads) {
    asm volatile("bar.sync %0, %1;" :: "r"(id), "r"(nthreads) : "memory");
}

// ---------------- kernel ----------------
__global__ void __launch_bounds__(NT, 1)
rnn_kernel(const float* __restrict__ gx,  const float* __restrict__ gWx,
           const float* __restrict__ gWh, const float* __restrict__ gbr,
           const float* __restrict__ gW1, const float* __restrict__ gb1,
           const float* __restrict__ gW2, const float* __restrict__ gb2,
           float* __restrict__ gout) {
    extern __shared__ char smem[];
    const int tid  = threadIdx.x;
    const int lane = tid & 31;
    const int wid  = tid >> 5;
    const int m0   = blockIdx.x * BM;
    const int gid  = lane >> 2;      // row group 0..7
    const int tig  = lane & 3;       // thread-in-group
    const int tq   = lane >> 3;      // ldmatrix address slot
    const int wr   = wid >> 2;       // row half (0..1): rows 64*wr..
    const int wc   = wid & 3;        // col quarter (0..3): cols 64*wc..

    // ---- cooperative staging ----
    for (int i = tid; i < Hn * Hn; i += NT) {            // Wh[k][n] -> k-major padded f16
        int k = i >> 8, n = i & 255;
        *(__half*)(smem + OFF_WH + k * WH_STRIDE + n * 2) = __float2half(gWh[i]);
    }
    for (int i = tid; i < Hn; i += NT)
        ((float2*)(smem + OFF_WXB))[i] = make_float2(gWx[i], gbr[i]);
    for (int i = tid; i < 64; i += NT)  ((float*)(smem + OFF_B1))[i] = gb1[i];
    for (int i = tid; i < 320; i += NT) ((float*)(smem + OFF_W2))[i] = gW2[i];
    if (tid < 5) ((float*)(smem + OFF_B2))[tid] = gb2[tid];
    __syncthreads();

    const uint32_t sb = smem_u32(smem);
    const float4* wxb4 = (const float4*)(smem + OFF_WXB);   // {w0,b0,w1,b1} per even col pair

    // ---- t = 0: h0 = tanh(x0*Wx + b) -> h smem (thread: row tid>>1, col half tid&1) ----
    {
        int row = tid >> 1, ch = (tid & 1) * 128;
        float x0 = gx[(size_t)(m0 + row) * Tn];
        #pragma unroll
        for (int j = 0; j < 64; ++j) {
            float4 wb = wxb4[ch / 2 + j];
            uint32_t p = tanh2(pack_f16x2(fmaf(x0, wb.x, wb.y), fmaf(x0, wb.z, wb.w)));
            *(uint32_t*)(smem + OFF_H + row * H_STRIDE + (ch + 2 * j) * 2) = p;
        }
    }
    bar_sync(1 + wr, 128);   // rows 0-63 written by tids 0-127 = warps 0-3 = group wr=0; ok

    // ---- per-warp addresses ----
    // A (non-trans) from h: m16k16 tile at (row 64wr+16mt, k 16kc)
    const uint32_t aBase = sb + OFF_H
        + (64 * wr + (tq & 1) * 8 + (lane & 7)) * H_STRIDE + (tq >> 1) * 16;
    // B (trans) from Wh: k16 x n16 at (k 16kc, n 64wc+16q)
    const uint32_t bBase = sb + OFF_WH
        + ((tq & 1) * 8 + (lane & 7)) * WH_STRIDE + (tq >> 1) * 16 + wc * 128;

    // x row offsets for this thread's 8 output rows (4 m-tiles x {gid, gid+8})
    int roff[8];
    #pragma unroll
    for (int mt = 0; mt < 4; ++mt) {
        roff[2 * mt]     = (m0 + 64 * wr + 16 * mt + gid) * Tn;
        roff[2 * mt + 1] = roff[2 * mt] + 8 * Tn;
    }
    float xn[8];
    #pragma unroll
    for (int j = 0; j < 8; ++j) xn[j] = gx[roff[j] + 1];

    // ---- recurrence: t = 1..186 ----
    #pragma unroll 1
    for (int t = 1; t < Tn; ++t) {
        float xv[8];
        #pragma unroll
        for (int j = 0; j < 8; ++j) xv[j] = xn[j];
        const int tnext = (t + 1 < Tn) ? t + 1 : t;
        #pragma unroll
        for (int j = 0; j < 8; ++j) xn[j] = gx[roff[j] + tnext];

        float d[4][8][4];
        #pragma unroll
        for (int mt = 0; mt < 4; ++mt)                   // D init = x_t*Wx + b
            #pragma unroll
            for (int j = 0; j < 8; ++j) {
                float4 wb = wxb4[32 * wc + 4 * j + tig];
                d[mt][j][0] = fmaf(xv[2 * mt],     wb.x, wb.y);
                d[mt][j][1] = fmaf(xv[2 * mt],     wb.z, wb.w);
                d[mt][j][2] = fmaf(xv[2 * mt + 1], wb.x, wb.y);
                d[mt][j][3] = fmaf(xv[2 * mt + 1], wb.z, wb.w);
            }
        #pragma unroll
        for (int kc = 0; kc < 16; ++kc) {
            uint32_t a[4][4];
            #pragma unroll
            for (int mt = 0; mt < 4; ++mt)
                ldsm4(a[mt][0], a[mt][1], a[mt][2], a[mt][3],
                      aBase + mt * 16 * H_STRIDE + kc * 32);
            const uint32_t bk = bBase + kc * 16 * WH_STRIDE;
            #pragma unroll
            for (int q = 0; q < 4; ++q) {                // n8-tiles 2q, 2q+1
                uint32_t b0, b1, b2, b3;
                ldsm4t(b0, b1, b2, b3, bk + q * 32);
                #pragma unroll
                for (int mt = 0; mt < 4; ++mt) {
                    mma16816(d[mt][2 * q],     a[mt][0], a[mt][1], a[mt][2], a[mt][3], b0, b1);
                    mma16816(d[mt][2 * q + 1], a[mt][0], a[mt][1], a[mt][2], a[mt][3], b2, b3);
                }
            }
        }
        bar_sync(1 + wr, 128);                           // group reads of h done
        #pragma unroll
        for (int mt = 0; mt < 4; ++mt) {
            int r0 = 64 * wr + 16 * mt + gid;
            #pragma unroll
            for (int j = 0; j < 8; ++j) {
                int cb = (64 * wc + 8 * j + 2 * tig) * 2;
                *(uint32_t*)(smem + OFF_H + r0 * H_STRIDE + cb) =
                    tanh2(pack_f16x2(d[mt][j][0], d[mt][j][1]));
                *(uint32_t*)(smem + OFF_H + (r0 + 8) * H_STRIDE + cb) =
                    tanh2(pack_f16x2(d[mt][j][2], d[mt][j][3]));
            }
        }
        bar_sync(1 + wr, 128);                           // group writes of h visible
    }

    // ---- head: stage W1 over dead Wh, hidden = relu(h@W1+b1), W2 + softmax ----
    __syncthreads();
    for (int i = tid; i < Hn * 64; i += NT) {            // W1[k][n]
        int k = i >> 6, n = i & 63;
        *(__half*)(smem + OFF_WH + k * W1_STRIDE + n * 2) = __float2half(gW1[i]);
    }
    __syncthreads();

    // warp handles rows 16*wid..16*wid+15
    const uint32_t aHead = sb + OFF_H
        + (16 * wid + (tq & 1) * 8 + (lane & 7)) * H_STRIDE + (tq >> 1) * 16;
    const uint32_t lds_w1 = sb + OFF_WH
        + ((tq & 1) * 8 + (lane & 7)) * W1_STRIDE + (tq >> 1) * 16;

    float hd[8][4];
    #pragma unroll
    for (int t2 = 0; t2 < 8; ++t2)
        hd[t2][0] = hd[t2][1] = hd[t2][2] = hd[t2][3] = 0.f;
    #pragma unroll
    for (int kc = 0; kc < 16; ++kc) {
        uint32_t a0, a1, a2, a3;
        ldsm4(a0, a1, a2, a3, aHead + kc * 32);
        const uint32_t base = lds_w1 + kc * 16 * W1_STRIDE;
        #pragma unroll
        for (int nt2 = 0; nt2 < 4; ++nt2) {
            uint32_t b0, b1, b2, b3;
            ldsm4t(b0, b1, b2, b3, base + nt2 * 32);
            mma16816(hd[2 * nt2],     a0, a1, a2, a3, b0, b1);
            mma16816(hd[2 * nt2 + 1], a0, a1, a2, a3, b2, b3);
        }
    }
    {
        const float* sb1 = (const float*)(smem + OFF_B1);
        const float* sw2 = (const float*)(smem + OFF_W2);
        const float* sb2 = (const float*)(smem + OFF_B2);
        float acc0[5] = {0, 0, 0, 0, 0}, acc8[5] = {0, 0, 0, 0, 0};
        #pragma unroll
        for (int t2 = 0; t2 < 8; ++t2) {
            int c0 = 8 * t2 + 2 * tig;
            float b1a = sb1[c0], b1b = sb1[c0 + 1];
            float h00 = fmaxf(hd[t2][0] + b1a, 0.f), h01 = fmaxf(hd[t2][1] + b1b, 0.f);
            float h80 = fmaxf(hd[t2][2] + b1a, 0.f), h81 = fmaxf(hd[t2][3] + b1b, 0.f);
            #pragma unroll
            for (int c = 0; c < 5; ++c) {
                acc0[c] = fmaf(h00, sw2[c0 * 5 + c], fmaf(h01, sw2[(c0 + 1) * 5 + c], acc0[c]));
                acc8[c] = fmaf(h80, sw2[c0 * 5 + c], fmaf(h81, sw2[(c0 + 1) * 5 + c], acc8[c]));
            }
        }
        #pragma unroll
        for (int c = 0; c < 5; ++c) {                    // reduce over 4-lane tig group
            acc0[c] += __shfl_xor_sync(0xFFFFFFFFu, acc0[c], 1);
            acc0[c] += __shfl_xor_sync(0xFFFFFFFFu, acc0[c], 2);
            acc8[c] += __shfl_xor_sync(0xFFFFFFFFu, acc8[c], 1);
            acc8[c] += __shfl_xor_sync(0xFFFFFFFFu, acc8[c], 2);
        }
        if (tig == 0) {
            int row0 = m0 + wid * 16 + gid;
            float o[5];
            #pragma unroll
            for (int c = 0; c < 5; ++c) o[c] = acc0[c] + sb2[c];
            float mx = fmaxf(fmaxf(fmaxf(o[0], o[1]), fmaxf(o[2], o[3])), o[4]);
            float s = 0.f;
            #pragma unroll
            for (int c = 0; c < 5; ++c) { o[c] = __expf(o[c] - mx); s += o[c]; }
            float inv = 1.f / s;
            #pragma unroll
            for (int c = 0; c < 5; ++c) gout[(size_t)row0 * 5 + c] = o[c] * inv;

            #pragma unroll
            for (int c = 0; c < 5; ++c) o[c] = acc8[c] + sb2[c];
            mx = fmaxf(fmaxf(fmaxf(o[0], o[1]), fmaxf(o[2], o[3])), o[4]);
            s = 0.f;
            #pragma unroll
            for (int c = 0; c < 5; ++c) { o[c] = __expf(o[c] - mx); s += o[c]; }
            inv = 1.f / s;
            #pragma unroll
            for (int c = 0; c < 5; ++c) gout[(size_t)(row0 + 8) * 5 + c] = o[c] * inv;
        }
    }
}

// ---------------- launch ----------------
extern "C" void kernel_launch(void* const* d_in, const int* in_sizes, int n_in,
                              void* d_out, int out_size) {
    const float* x  = (const float*)d_in[0];
    const float* Wx = (const float*)d_in[1];
    const float* Wh = (const float*)d_in[2];
    const float* br = (const float*)d_in[3];
    const float* W1 = (const float*)d_in[4];
    const float* b1 = (const float*)d_in[5];
    const float* W2 = (const float*)d_in[6];
    const float* b2 = (const float*)d_in[7];

    cudaFuncSetAttribute(rnn_kernel, cudaFuncAttributeMaxDynamicSharedMemorySize, SMEM_TOTAL);
    rnn_kernel<<<256, NT, SMEM_TOTAL>>>(x, Wx, Wh, br, W1, b1, W2, b2, (float*)d_out);
}